// round 10
// baseline (speedup 1.0000x reference)
#include <cuda_runtime.h>
#include <cuda_fp16.h>
#include <cstdint>

#define N_NODES 100000
#define N_EDGES 800000
#define C 64

#define SCAN_CHUNK 1024
#define NB_SCAN ((N_NODES + SCAN_CHUNK - 1) / SCAN_CHUNK)  // 98
#define G1_ROWS 128
#define G1_TILES ((N_NODES + G1_ROWS - 1) / G1_ROWS)       // 782
#define COUNT_BLOCKS ((N_EDGES / 4 + 255) / 256)           // 782
#define EPI_ROWS 64
#define EPI_TILES ((N_NODES + EPI_ROWS - 1) / EPI_ROWS)    // 1563
#define FILL_BLOCKS ((N_EDGES + 255) / 256)                // 3125

// Scratch (device globals — zero-initialized at module load; g_cnt's
// "zero on entry" invariant is restored by k_gather_epi every run)
__device__ __half2 g_hh[(size_t)N_NODES * 32]; // x@W UNSCALED, fp16x2 (12.8MB)
__device__ int     g_cnt[N_NODES];             // in-degree (excl. self-loop)
__device__ float   g_dinv[N_NODES];            // rsqrt(1 + cnt)
__device__ int     g_off[N_NODES];             // CSR row starts
__device__ int     g_cursor[N_NODES];          // bucket-fill cursors
__device__ int     g_srcs[N_EDGES];            // CSR column (src) indices

// ---- Blackwell packed f32x2 helpers (FFMA2: 2 fp32 FMAs per issue) --------
__device__ __forceinline__ unsigned long long pack2(float lo, float hi) {
    unsigned long long r;
    asm("mov.b64 %0, {%1, %2};" : "=l"(r) : "f"(lo), "f"(hi));
    return r;
}
__device__ __forceinline__ void unpack2(unsigned long long v, float& lo, float& hi) {
    asm("mov.b64 {%0, %1}, %2;" : "=f"(lo), "=f"(hi) : "l"(v));
}
__device__ __forceinline__ unsigned long long ffma2(unsigned long long a,
                                                    unsigned long long b,
                                                    unsigned long long c) {
    unsigned long long d;
    asm("fma.rn.f32x2 %0, %1, %2, %3;" : "=l"(d) : "l"(a), "l"(b), "l"(c));
    return d;
}

// ---------------------------------------------------------------------------
// K1: merged GEMM1 + degree count.
// Blocks [0, G1_TILES): hh = x @ W (UNSCALED) -> fp16, 8x4 micro-tile, f32x2.
// Blocks [G1_TILES, +COUNT_BLOCKS): histogram over dst, 4 edges/thread.
// ---------------------------------------------------------------------------
__global__ __launch_bounds__(256) void k_count_gemm(const float* __restrict__ x,
                                                    const float* __restrict__ W,
                                                    const int* __restrict__ ei) {
    __shared__ float Ws[64 * 64];      // k-major
    __shared__ float xs[G1_ROWS][68];

    int tid = threadIdx.x;

    if (blockIdx.x >= G1_TILES) {
        // ---- count part ----
        int idx = (blockIdx.x - G1_TILES) * 256 + tid;   // edge quad index
        int e4 = idx * 4;
        if (e4 + 3 < N_EDGES) {
            int4 d = *(const int4*)&ei[N_EDGES + e4];
            atomicAdd(&g_cnt[d.x], 1);
            atomicAdd(&g_cnt[d.y], 1);
            atomicAdd(&g_cnt[d.z], 1);
            atomicAdd(&g_cnt[d.w], 1);
        } else {
            for (int j = 0; j < 4; j++)
                if (e4 + j < N_EDGES) atomicAdd(&g_cnt[ei[N_EDGES + e4 + j]], 1);
        }
        return;
    }

    // ---- GEMM part ----
    long long rowbase = (long long)blockIdx.x * G1_ROWS;

#pragma unroll
    for (int i = 0; i < 4; i++)
        ((float4*)Ws)[tid + 256 * i] = ((const float4*)W)[tid + 256 * i];

#pragma unroll
    for (int i = 0; i < 8; i++) {
        int f = tid + i * 256;
        int r = f >> 4, kq = f & 15;
        long long grow = rowbase + r;
        float4 v = make_float4(0.f, 0.f, 0.f, 0.f);
        if (grow < N_NODES) v = *(const float4*)&x[grow * 64 + kq * 4];
        *(float4*)&xs[r][kq * 4] = v;
    }
    __syncthreads();

    int tx = tid & 15;
    int ty = tid >> 4;
    int r0 = ty * 8;
    int c0 = tx * 4;

    unsigned long long a01[8], a23[8];
#pragma unroll
    for (int i = 0; i < 8; i++) { a01[i] = 0ull; a23[i] = 0ull; }

#pragma unroll
    for (int k0 = 0; k0 < 64; k0 += 4) {
        float4 xv[8];
#pragma unroll
        for (int i = 0; i < 8; i++) xv[i] = *(float4*)&xs[r0 + i][k0];
#pragma unroll
        for (int kk = 0; kk < 4; kk++) {
            float4 w = *(float4*)&Ws[(k0 + kk) * 64 + c0];
            unsigned long long w01 = pack2(w.x, w.y);
            unsigned long long w23 = pack2(w.z, w.w);
#pragma unroll
            for (int i = 0; i < 8; i++) {
                float xk = (kk == 0) ? xv[i].x : (kk == 1) ? xv[i].y
                         : (kk == 2) ? xv[i].z : xv[i].w;
                unsigned long long xx = pack2(xk, xk);
                a01[i] = ffma2(xx, w01, a01[i]);
                a23[i] = ffma2(xx, w23, a23[i]);
            }
        }
    }

#pragma unroll
    for (int i = 0; i < 8; i++) {
        long long row = rowbase + r0 + i;
        if (row < N_NODES) {
            float b0, b1, b2, b3;
            unpack2(a01[i], b0, b1);
            unpack2(a23[i], b2, b3);
            __half2* dst = &g_hh[row * 32 + (c0 >> 1)];
            dst[0] = __floats2half2_rn(b0, b1);
            dst[1] = __floats2half2_rn(b2, b3);
        }
    }
}

// ---------------------------------------------------------------------------
// K2: single-kernel scan. Block b first sums all counts BEFORE its chunk
// (redundant work <= 388KB/block, cheaper than a serialized extra launch),
// then block-local scan of its own 1024 counts -> offsets, cursors, dinv.
// ---------------------------------------------------------------------------
__global__ __launch_bounds__(256) void k_scan() {
    __shared__ int wsum[8], woff[8];
    __shared__ int sBase;
    int tid = threadIdx.x;
    int lane = tid & 31, wid = tid >> 5;

    // ---- base = sum of counts in chunks [0, blockIdx.x) ----
    int nPre = blockIdx.x * SCAN_CHUNK;   // multiple of 1024, fully in-range
    int pre = 0;
    for (int i = tid * 4; i < nPre; i += 256 * 4) {
        int4 v = *(const int4*)&g_cnt[i];
        pre += v.x + v.y + v.z + v.w;
    }
#pragma unroll
    for (int o = 16; o; o >>= 1) pre += __shfl_down_sync(0xFFFFFFFFu, pre, o);
    if (lane == 0) wsum[wid] = pre;
    __syncthreads();
    if (tid == 0) {
        int t = 0;
#pragma unroll
        for (int i = 0; i < 8; i++) t += wsum[i];
        sBase = t;
    }
    __syncthreads();   // sBase visible; wsum free for reuse

    // ---- own-chunk scan ----
    int base = blockIdx.x * SCAN_CHUNK + tid * 4;
    int v[4];
    if (base + 3 < N_NODES) {
        int4 t = *(const int4*)&g_cnt[base];
        v[0] = t.x; v[1] = t.y; v[2] = t.z; v[3] = t.w;
    } else {
#pragma unroll
        for (int j = 0; j < 4; j++)
            v[j] = (base + j < N_NODES) ? g_cnt[base + j] : 0;
    }
    int tsum = v[0] + v[1] + v[2] + v[3];

    int inc = tsum;
#pragma unroll
    for (int o = 1; o < 32; o <<= 1) {
        int y = __shfl_up_sync(0xFFFFFFFFu, inc, o);
        if (lane >= o) inc += y;
    }
    if (lane == 31) wsum[wid] = inc;
    __syncthreads();
    if (wid == 0) {
        int s = (lane < 8) ? wsum[lane] : 0;
        int orig = s;
#pragma unroll
        for (int o = 1; o < 8; o <<= 1) {
            int y = __shfl_up_sync(0xFFFFFFFFu, s, o);
            if (lane >= o) s += y;
        }
        if (lane < 8) woff[lane] = s - orig;
    }
    __syncthreads();

    int off = sBase + woff[wid] + (inc - tsum);
#pragma unroll
    for (int j = 0; j < 4; j++) {
        int i = base + j;
        if (i < N_NODES) {
            g_off[i] = off;
            g_cursor[i] = off;
            g_dinv[i] = rsqrtf(1.0f + (float)v[j]);
        }
        off += v[j];
    }
}

// ---------------------------------------------------------------------------
// K3: bucket fill — 1 edge per thread (max independent atomic chains;
// previous 4-edges/thread version measured issue=1.7%, pure latency-bound)
// ---------------------------------------------------------------------------
__global__ __launch_bounds__(256) void k_fill(const int* __restrict__ ei) {
    int e = blockIdx.x * 256 + threadIdx.x;
    if (e < N_EDGES) {
        int src = ei[e];
        int dst = ei[N_EDGES + e];
        g_srcs[atomicAdd(&g_cursor[dst], 1)] = src;
    }
}

// ---------------------------------------------------------------------------
// K4: fused gather + epilogue. 512 threads, 64 rows per block:
// 16 warps x 4 nodes each (64 warps/SM for gather-latency hiding).
// Gather: a = h[row]*dinv[row] + sum h[src]*dinv[src]; gcn = a*dinv[row]+b.
// LN + ReLU + x-gate into smem; then 2x4 register-tiled f32x2 GEMM2.
// Also restores the g_cnt==0 invariant for the next run.
// ---------------------------------------------------------------------------
__global__ __launch_bounds__(512) void k_gather_epi(
        const float* __restrict__ x,
        const float* __restrict__ b,
        const float* __restrict__ gamma,
        const float* __restrict__ beta,
        const float* __restrict__ fcW,
        const float* __restrict__ fcb,
        float* __restrict__ out) {
    __shared__ float Ws[64 * 64];
    __shared__ float rs[64][68];
    __shared__ float sb[64], sg[64], sbe[64], sfcb[64];

    int tid = threadIdx.x;
    long long rowbase = (long long)blockIdx.x * EPI_ROWS;

#pragma unroll
    for (int i = 0; i < 2; i++)
        ((float4*)Ws)[tid + 512 * i] = ((const float4*)fcW)[tid + 512 * i];
    if (tid < 64) {
        sb[tid] = b[tid];
        sg[tid] = gamma[tid];
        sbe[tid] = beta[tid];
        sfcb[tid] = fcb[tid];
    }
    __syncthreads();

    int w = tid >> 5;   // warp 0..15
    int l = tid & 31;

#pragma unroll
    for (int rr = 0; rr < 4; rr++) {
        int lr = w * 4 + rr;
        long long row = rowbase + lr;
        if (row < N_NODES) {
            int start = g_off[row];
            int deg = g_cnt[row];
            float dinv = g_dinv[row];

            // self-loop term: h[row] * dinv[row]
            float2 hv = __half22float2(g_hh[row * 32 + l]);
            float2 a = make_float2(hv.x * dinv, hv.y * dinv);

            int e = start, end = start + deg;
            for (; e + 3 < end; e += 4) {
                int s0 = g_srcs[e],     s1 = g_srcs[e + 1];
                int s2 = g_srcs[e + 2], s3 = g_srcs[e + 3];
                float d0 = g_dinv[s0], d1 = g_dinv[s1];
                float d2 = g_dinv[s2], d3 = g_dinv[s3];
                float2 v0 = __half22float2(g_hh[(long long)s0 * 32 + l]);
                float2 v1 = __half22float2(g_hh[(long long)s1 * 32 + l]);
                float2 v2 = __half22float2(g_hh[(long long)s2 * 32 + l]);
                float2 v3 = __half22float2(g_hh[(long long)s3 * 32 + l]);
                a.x += v0.x * d0 + v1.x * d1 + v2.x * d2 + v3.x * d3;
                a.y += v0.y * d0 + v1.y * d1 + v2.y * d2 + v3.y * d3;
            }
            for (; e < end; e++) {
                int s = g_srcs[e];
                float ds = g_dinv[s];
                float2 v = __half22float2(g_hh[(long long)s * 32 + l]);
                a.x += v.x * ds;
                a.y += v.y * ds;
            }

            float v0 = a.x * dinv + sb[2 * l];
            float v1 = a.y * dinv + sb[2 * l + 1];

            float s = v0 + v1;
            float q = v0 * v0 + v1 * v1;
#pragma unroll
            for (int o = 16; o; o >>= 1) {
                s += __shfl_xor_sync(0xFFFFFFFFu, s, o);
                q += __shfl_xor_sync(0xFFFFFFFFu, q, o);
            }
            float mu = s * (1.0f / 64.0f);
            float var = q * (1.0f / 64.0f) - mu * mu;
            float inv = rsqrtf(var + 1e-5f);

            float2 xv = *(const float2*)&x[row * 64 + 2 * l];
            rs[lr][2 * l]     = fmaxf((v0 - mu) * inv * sg[2 * l]     + sbe[2 * l],     0.f) * xv.x;
            rs[lr][2 * l + 1] = fmaxf((v1 - mu) * inv * sg[2 * l + 1] + sbe[2 * l + 1], 0.f) * xv.y;
        } else {
            rs[lr][2 * l] = 0.f;
            rs[lr][2 * l + 1] = 0.f;
        }
    }
    __syncthreads();

    // restore g_cnt == 0 for the next run (reads all happened in phase 1)
    if (tid < 64) {
        long long row = rowbase + tid;
        if (row < N_NODES) g_cnt[row] = 0;
    }

    // ---- GEMM2: out = rs @ fcW + fcb (2x4 register tile, f32x2) ----
    int tx = tid & 15;        // col group 0..15
    int ty = tid >> 4;        // row group 0..31
    int r0 = ty * 2;
    int c0 = tx * 4;

    unsigned long long a01[2], a23[2];
#pragma unroll
    for (int i = 0; i < 2; i++) { a01[i] = 0ull; a23[i] = 0ull; }

#pragma unroll
    for (int k0 = 0; k0 < 64; k0 += 4) {
        float4 xv[2];
#pragma unroll
        for (int i = 0; i < 2; i++) xv[i] = *(float4*)&rs[r0 + i][k0];
#pragma unroll
        for (int kk = 0; kk < 4; kk++) {
            float4 wv = *(float4*)&Ws[(k0 + kk) * 64 + c0];
            unsigned long long w01 = pack2(wv.x, wv.y);
            unsigned long long w23 = pack2(wv.z, wv.w);
#pragma unroll
            for (int i = 0; i < 2; i++) {
                float xk = (kk == 0) ? xv[i].x : (kk == 1) ? xv[i].y
                         : (kk == 2) ? xv[i].z : xv[i].w;
                unsigned long long xx = pack2(xk, xk);
                a01[i] = ffma2(xx, w01, a01[i]);
                a23[i] = ffma2(xx, w23, a23[i]);
            }
        }
    }

#pragma unroll
    for (int i = 0; i < 2; i++) {
        long long row = rowbase + r0 + i;
        if (row < N_NODES) {
            float b0, b1, b2, b3;
            unpack2(a01[i], b0, b1);
            unpack2(a23[i], b2, b3);
            *(float4*)&out[row * 64 + c0] =
                make_float4(b0 + sfcb[c0], b1 + sfcb[c0 + 1],
                            b2 + sfcb[c0 + 2], b3 + sfcb[c0 + 3]);
        }
    }
}

// ---------------------------------------------------------------------------
extern "C" void kernel_launch(void* const* d_in, const int* in_sizes, int n_in,
                              void* d_out, int out_size) {
    const float* x     = (const float*)d_in[0];
    const int*   ei    = (const int*)d_in[1];   // int32 per harness metadata
    const float* W     = (const float*)d_in[2];
    const float* b     = (const float*)d_in[3];
    const float* gamma = (const float*)d_in[4];
    const float* beta  = (const float*)d_in[5];
    const float* fcW   = (const float*)d_in[6];
    const float* fcb   = (const float*)d_in[7];
    float* out = (float*)d_out;

    (void)in_sizes; (void)n_in; (void)out_size;

    k_count_gemm<<<G1_TILES + COUNT_BLOCKS, 256>>>(x, W, ei);
    k_scan<<<NB_SCAN, 256>>>();
    k_fill<<<FILL_BLOCKS, 256>>>(ei);
    k_gather_epi<<<EPI_TILES, 512>>>(x, b, gamma, beta, fcW, fcb, out);
}

// round 11
// speedup vs baseline: 1.0280x; 1.0280x over previous
#include <cuda_runtime.h>
#include <cuda_fp16.h>
#include <cstdint>

#define N_NODES 100000
#define N_EDGES 800000
#define C 64

#define SCAN_CHUNK 1024
#define NB_SCAN ((N_NODES + SCAN_CHUNK - 1) / SCAN_CHUNK)  // 98
#define G1_ROWS 128
#define G1_TILES ((N_NODES + G1_ROWS - 1) / G1_ROWS)       // 782
#define COUNT_BLOCKS ((N_EDGES / 4 + 255) / 256)           // 782
#define EPI_ROWS 64
#define EPI_TILES ((N_NODES + EPI_ROWS - 1) / EPI_ROWS)    // 1563
#define FILL_BLOCKS ((N_EDGES + 255) / 256)                // 3125

// Scratch (device globals — zero-initialized at module load; g_cnt's
// "zero on entry" invariant is restored by k_gather_epi every run)
__device__ __half2 g_hh[(size_t)N_NODES * 32]; // x@W UNSCALED, fp16x2 (12.8MB)
__device__ int     g_cnt[N_NODES];             // in-degree (excl. self-loop)
__device__ float   g_dinv[N_NODES];            // rsqrt(1 + cnt)
__device__ int     g_off[N_NODES];             // CSR row starts
__device__ int     g_cursor[N_NODES];          // bucket-fill cursors
__device__ int     g_srcs[N_EDGES];            // CSR column (src) indices

// ---- Blackwell packed f32x2 helpers (FFMA2: 2 fp32 FMAs per issue) --------
__device__ __forceinline__ unsigned long long pack2(float lo, float hi) {
    unsigned long long r;
    asm("mov.b64 %0, {%1, %2};" : "=l"(r) : "f"(lo), "f"(hi));
    return r;
}
__device__ __forceinline__ void unpack2(unsigned long long v, float& lo, float& hi) {
    asm("mov.b64 {%0, %1}, %2;" : "=f"(lo), "=f"(hi) : "l"(v));
}
__device__ __forceinline__ unsigned long long ffma2(unsigned long long a,
                                                    unsigned long long b,
                                                    unsigned long long c) {
    unsigned long long d;
    asm("fma.rn.f32x2 %0, %1, %2, %3;" : "=l"(d) : "l"(a), "l"(b), "l"(c));
    return d;
}

// ---------------------------------------------------------------------------
// K1: merged GEMM1 + degree count.
// Blocks [0, G1_TILES): hh = x @ W (UNSCALED) -> fp16, 8x4 micro-tile, f32x2.
// Blocks [G1_TILES, +COUNT_BLOCKS): histogram over dst, 4 edges/thread.
// ---------------------------------------------------------------------------
__global__ __launch_bounds__(256) void k_count_gemm(const float* __restrict__ x,
                                                    const float* __restrict__ W,
                                                    const int* __restrict__ ei) {
    __shared__ float Ws[64 * 64];      // k-major
    __shared__ float xs[G1_ROWS][68];

    int tid = threadIdx.x;

    if (blockIdx.x >= G1_TILES) {
        int idx = (blockIdx.x - G1_TILES) * 256 + tid;
        int e4 = idx * 4;
        if (e4 + 3 < N_EDGES) {
            int4 d = *(const int4*)&ei[N_EDGES + e4];
            atomicAdd(&g_cnt[d.x], 1);
            atomicAdd(&g_cnt[d.y], 1);
            atomicAdd(&g_cnt[d.z], 1);
            atomicAdd(&g_cnt[d.w], 1);
        } else {
            for (int j = 0; j < 4; j++)
                if (e4 + j < N_EDGES) atomicAdd(&g_cnt[ei[N_EDGES + e4 + j]], 1);
        }
        return;
    }

    long long rowbase = (long long)blockIdx.x * G1_ROWS;

#pragma unroll
    for (int i = 0; i < 4; i++)
        ((float4*)Ws)[tid + 256 * i] = ((const float4*)W)[tid + 256 * i];

#pragma unroll
    for (int i = 0; i < 8; i++) {
        int f = tid + i * 256;
        int r = f >> 4, kq = f & 15;
        long long grow = rowbase + r;
        float4 v = make_float4(0.f, 0.f, 0.f, 0.f);
        if (grow < N_NODES) v = *(const float4*)&x[grow * 64 + kq * 4];
        *(float4*)&xs[r][kq * 4] = v;
    }
    __syncthreads();

    int tx = tid & 15;
    int ty = tid >> 4;
    int r0 = ty * 8;
    int c0 = tx * 4;

    unsigned long long a01[8], a23[8];
#pragma unroll
    for (int i = 0; i < 8; i++) { a01[i] = 0ull; a23[i] = 0ull; }

#pragma unroll
    for (int k0 = 0; k0 < 64; k0 += 4) {
        float4 xv[8];
#pragma unroll
        for (int i = 0; i < 8; i++) xv[i] = *(float4*)&xs[r0 + i][k0];
#pragma unroll
        for (int kk = 0; kk < 4; kk++) {
            float4 w = *(float4*)&Ws[(k0 + kk) * 64 + c0];
            unsigned long long w01 = pack2(w.x, w.y);
            unsigned long long w23 = pack2(w.z, w.w);
#pragma unroll
            for (int i = 0; i < 8; i++) {
                float xk = (kk == 0) ? xv[i].x : (kk == 1) ? xv[i].y
                         : (kk == 2) ? xv[i].z : xv[i].w;
                unsigned long long xx = pack2(xk, xk);
                a01[i] = ffma2(xx, w01, a01[i]);
                a23[i] = ffma2(xx, w23, a23[i]);
            }
        }
    }

#pragma unroll
    for (int i = 0; i < 8; i++) {
        long long row = rowbase + r0 + i;
        if (row < N_NODES) {
            float b0, b1, b2, b3;
            unpack2(a01[i], b0, b1);
            unpack2(a23[i], b2, b3);
            __half2* dst = &g_hh[row * 32 + (c0 >> 1)];
            dst[0] = __floats2half2_rn(b0, b1);
            dst[1] = __floats2half2_rn(b2, b3);
        }
    }
}

// ---------------------------------------------------------------------------
// K2: single-kernel scan. Block b first sums all counts BEFORE its chunk,
// then block-local scan of its own 1024 counts -> offsets, cursors, dinv.
// ---------------------------------------------------------------------------
__global__ __launch_bounds__(256) void k_scan() {
    __shared__ int wsum[8], woff[8];
    __shared__ int sBase;
    int tid = threadIdx.x;
    int lane = tid & 31, wid = tid >> 5;

    int nPre = blockIdx.x * SCAN_CHUNK;
    int pre = 0;
#pragma unroll 4
    for (int i = tid * 4; i < nPre; i += 256 * 4) {
        int4 v = *(const int4*)&g_cnt[i];
        pre += v.x + v.y + v.z + v.w;
    }
#pragma unroll
    for (int o = 16; o; o >>= 1) pre += __shfl_down_sync(0xFFFFFFFFu, pre, o);
    if (lane == 0) wsum[wid] = pre;
    __syncthreads();
    if (tid == 0) {
        int t = 0;
#pragma unroll
        for (int i = 0; i < 8; i++) t += wsum[i];
        sBase = t;
    }
    __syncthreads();

    int base = blockIdx.x * SCAN_CHUNK + tid * 4;
    int v[4];
    if (base + 3 < N_NODES) {
        int4 t = *(const int4*)&g_cnt[base];
        v[0] = t.x; v[1] = t.y; v[2] = t.z; v[3] = t.w;
    } else {
#pragma unroll
        for (int j = 0; j < 4; j++)
            v[j] = (base + j < N_NODES) ? g_cnt[base + j] : 0;
    }
    int tsum = v[0] + v[1] + v[2] + v[3];

    int inc = tsum;
#pragma unroll
    for (int o = 1; o < 32; o <<= 1) {
        int y = __shfl_up_sync(0xFFFFFFFFu, inc, o);
        if (lane >= o) inc += y;
    }
    if (lane == 31) wsum[wid] = inc;
    __syncthreads();
    if (wid == 0) {
        int s = (lane < 8) ? wsum[lane] : 0;
        int orig = s;
#pragma unroll
        for (int o = 1; o < 8; o <<= 1) {
            int y = __shfl_up_sync(0xFFFFFFFFu, s, o);
            if (lane >= o) s += y;
        }
        if (lane < 8) woff[lane] = s - orig;
    }
    __syncthreads();

    int off = sBase + woff[wid] + (inc - tsum);
#pragma unroll
    for (int j = 0; j < 4; j++) {
        int i = base + j;
        if (i < N_NODES) {
            g_off[i] = off;
            g_cursor[i] = off;
            g_dinv[i] = rsqrtf(1.0f + (float)v[j]);
        }
        off += v[j];
    }
}

// ---------------------------------------------------------------------------
// K3: bucket fill — 1 edge per thread (max independent atomic chains)
// ---------------------------------------------------------------------------
__global__ __launch_bounds__(256) void k_fill(const int* __restrict__ ei) {
    int e = blockIdx.x * 256 + threadIdx.x;
    if (e < N_EDGES) {
        int src = ei[e];
        int dst = ei[N_EDGES + e];
        g_srcs[atomicAdd(&g_cursor[dst], 1)] = src;
    }
}

// ---------------------------------------------------------------------------
// K4: fused gather + epilogue. 256 threads, 64 rows/block: 8 warps x 8 nodes.
// Gather is MLP-restructured: lane-coalesced srcs+dinv staging (1 LDG covers
// 32 neighbors), then 8-deep batches of INDEPENDENT g_hh loads with shfl-
// broadcast indices — breaks the srcs->hh 2-deep serial chain that made the
// R10 version 76.7us at issue=41%.
// Then LN + ReLU + x-gate into smem; 4x4 register-tiled f32x2 GEMM2.
// Restores the g_cnt==0 invariant for the next run.
// ---------------------------------------------------------------------------
__global__ __launch_bounds__(256) void k_gather_epi(
        const float* __restrict__ x,
        const float* __restrict__ b,
        const float* __restrict__ gamma,
        const float* __restrict__ beta,
        const float* __restrict__ fcW,
        const float* __restrict__ fcb,
        float* __restrict__ out) {
    __shared__ float Ws[64 * 64];
    __shared__ float rs[64][68];
    __shared__ float sb[64], sg[64], sbe[64], sfcb[64];

    int tid = threadIdx.x;
    long long rowbase = (long long)blockIdx.x * EPI_ROWS;

#pragma unroll
    for (int i = 0; i < 4; i++)
        ((float4*)Ws)[tid + 256 * i] = ((const float4*)fcW)[tid + 256 * i];
    if (tid < 64) {
        sb[tid] = b[tid];
        sg[tid] = gamma[tid];
        sbe[tid] = beta[tid];
        sfcb[tid] = fcb[tid];
    }
    __syncthreads();

    int w = tid >> 5;
    int l = tid & 31;

#pragma unroll
    for (int rr = 0; rr < 8; rr++) {
        int lr = w * 8 + rr;
        long long row = rowbase + lr;
        if (row < N_NODES) {
            int start = g_off[row];
            int deg = g_cnt[row];
            int end = start + deg;
            float dinv = g_dinv[row];

            // self-loop term: h[row] * dinv[row]
            float2 hv0 = __half22float2(g_hh[row * 32 + l]);
            float ax = hv0.x * dinv, ay = hv0.y * dinv;

            for (int base2 = start; base2 < end; base2 += 32) {
                // stage up to 32 neighbor (src, dinv) pairs lane-parallel
                int idx = base2 + l;
                int s_l = 0;
                float d_l = 0.f;
                if (idx < end) {
                    s_l = g_srcs[idx];            // coalesced
                    d_l = g_dinv[s_l];            // independent gather
                }
                int nb = min(32, end - base2);
                for (int j = 0; j < nb; j += 8) {
                    // 8 independent h-row loads (indices via shfl, d=0 for
                    // past-end slots -> contribution 0, loads stay in-bounds)
                    float hx[8], hy[8], dd[8];
#pragma unroll
                    for (int u = 0; u < 8; u++) {
                        int s = __shfl_sync(0xFFFFFFFFu, s_l, j + u);
                        dd[u] = __shfl_sync(0xFFFFFFFFu, d_l, j + u);
                        float2 hv = __half22float2(g_hh[(long long)s * 32 + l]);
                        hx[u] = hv.x;
                        hy[u] = hv.y;
                    }
#pragma unroll
                    for (int u = 0; u < 8; u++) {
                        ax += hx[u] * dd[u];
                        ay += hy[u] * dd[u];
                    }
                }
            }

            float v0 = ax * dinv + sb[2 * l];
            float v1 = ay * dinv + sb[2 * l + 1];

            float s = v0 + v1;
            float q = v0 * v0 + v1 * v1;
#pragma unroll
            for (int o = 16; o; o >>= 1) {
                s += __shfl_xor_sync(0xFFFFFFFFu, s, o);
                q += __shfl_xor_sync(0xFFFFFFFFu, q, o);
            }
            float mu = s * (1.0f / 64.0f);
            float var = q * (1.0f / 64.0f) - mu * mu;
            float inv = rsqrtf(var + 1e-5f);

            float2 xv = *(const float2*)&x[row * 64 + 2 * l];
            rs[lr][2 * l]     = fmaxf((v0 - mu) * inv * sg[2 * l]     + sbe[2 * l],     0.f) * xv.x;
            rs[lr][2 * l + 1] = fmaxf((v1 - mu) * inv * sg[2 * l + 1] + sbe[2 * l + 1], 0.f) * xv.y;
        } else {
            rs[lr][2 * l] = 0.f;
            rs[lr][2 * l + 1] = 0.f;
        }
    }
    __syncthreads();

    // restore g_cnt == 0 for the next run (reads all happened above)
    if (tid < 64) {
        long long row = rowbase + tid;
        if (row < N_NODES) g_cnt[row] = 0;
    }

    // ---- GEMM2: out = rs @ fcW + fcb (4x4 register tile, f32x2) ----
    int tx = tid & 15;
    int ty = tid >> 4;
    int r0 = ty * 4;
    int c0 = tx * 4;

    unsigned long long a01[4], a23[4];
#pragma unroll
    for (int i = 0; i < 4; i++) { a01[i] = 0ull; a23[i] = 0ull; }

#pragma unroll
    for (int k0 = 0; k0 < 64; k0 += 4) {
        float4 xv[4];
#pragma unroll
        for (int i = 0; i < 4; i++) xv[i] = *(float4*)&rs[r0 + i][k0];
#pragma unroll
        for (int kk = 0; kk < 4; kk++) {
            float4 wv = *(float4*)&Ws[(k0 + kk) * 64 + c0];
            unsigned long long w01 = pack2(wv.x, wv.y);
            unsigned long long w23 = pack2(wv.z, wv.w);
#pragma unroll
            for (int i = 0; i < 4; i++) {
                float xk = (kk == 0) ? xv[i].x : (kk == 1) ? xv[i].y
                         : (kk == 2) ? xv[i].z : xv[i].w;
                unsigned long long xx = pack2(xk, xk);
                a01[i] = ffma2(xx, w01, a01[i]);
                a23[i] = ffma2(xx, w23, a23[i]);
            }
        }
    }

#pragma unroll
    for (int i = 0; i < 4; i++) {
        long long row = rowbase + r0 + i;
        if (row < N_NODES) {
            float b0, b1, b2, b3;
            unpack2(a01[i], b0, b1);
            unpack2(a23[i], b2, b3);
            *(float4*)&out[row * 64 + c0] =
                make_float4(b0 + sfcb[c0], b1 + sfcb[c0 + 1],
                            b2 + sfcb[c0 + 2], b3 + sfcb[c0 + 3]);
        }
    }
}

// ---------------------------------------------------------------------------
extern "C" void kernel_launch(void* const* d_in, const int* in_sizes, int n_in,
                              void* d_out, int out_size) {
    const float* x     = (const float*)d_in[0];
    const int*   ei    = (const int*)d_in[1];   // int32 per harness metadata
    const float* W     = (const float*)d_in[2];
    const float* b     = (const float*)d_in[3];
    const float* gamma = (const float*)d_in[4];
    const float* beta  = (const float*)d_in[5];
    const float* fcW   = (const float*)d_in[6];
    const float* fcb   = (const float*)d_in[7];
    float* out = (float*)d_out;

    (void)in_sizes; (void)n_in; (void)out_size;

    k_count_gemm<<<G1_TILES + COUNT_BLOCKS, 256>>>(x, W, ei);
    k_scan<<<NB_SCAN, 256>>>();
    k_fill<<<FILL_BLOCKS, 256>>>(ei);
    k_gather_epi<<<EPI_TILES, 256>>>(x, b, gamma, beta, fcW, fcb, out);
}

// round 12
// speedup vs baseline: 1.0283x; 1.0003x over previous
#include <cuda_runtime.h>
#include <cuda_fp16.h>
#include <cstdint>

#define N_NODES 100000
#define N_EDGES 800000
#define C 64

#define SCAN_CHUNK 1024
#define NB_SCAN ((N_NODES + SCAN_CHUNK - 1) / SCAN_CHUNK)  // 98
#define G1_ROWS 128
#define G1_TILES ((N_NODES + G1_ROWS - 1) / G1_ROWS)       // 782
#define COUNT_BLOCKS ((N_EDGES / 4 + 255) / 256)           // 782
#define GL_ROWS 64
#define GL_TILES ((N_NODES + GL_ROWS - 1) / GL_ROWS)       // 1563
#define G2_ROWS 128
#define G2_TILES ((N_NODES + G2_ROWS - 1) / G2_ROWS)       // 782
#define FILL_BLOCKS ((N_EDGES + 255) / 256)                // 3125

// Scratch (device globals — zero-initialized at module load; g_cnt's
// "zero on entry" invariant is restored by k_gemm2 every run)
__device__ __half2 g_hh[(size_t)N_NODES * 32]; // x@W UNSCALED, fp16x2 (12.8MB)
__device__ __half2 g_rs[(size_t)N_NODES * 32]; // gated LN output, fp16x2 (12.8MB)
__device__ int     g_cnt[N_NODES];             // in-degree (excl. self-loop)
__device__ float   g_dinv[N_NODES];            // rsqrt(1 + cnt)
__device__ int     g_off[N_NODES];             // CSR row starts
__device__ int     g_cursor[N_NODES];          // bucket-fill cursors
__device__ int     g_srcs[N_EDGES];            // CSR column (src) indices

// ---- Blackwell packed f32x2 helpers (FFMA2: 2 fp32 FMAs per issue) --------
__device__ __forceinline__ unsigned long long pack2(float lo, float hi) {
    unsigned long long r;
    asm("mov.b64 %0, {%1, %2};" : "=l"(r) : "f"(lo), "f"(hi));
    return r;
}
__device__ __forceinline__ void unpack2(unsigned long long v, float& lo, float& hi) {
    asm("mov.b64 {%0, %1}, %2;" : "=f"(lo), "=f"(hi) : "l"(v));
}
__device__ __forceinline__ unsigned long long ffma2(unsigned long long a,
                                                    unsigned long long b,
                                                    unsigned long long c) {
    unsigned long long d;
    asm("fma.rn.f32x2 %0, %1, %2, %3;" : "=l"(d) : "l"(a), "l"(b), "l"(c));
    return d;
}

// ---------------------------------------------------------------------------
// K1: merged GEMM1 + degree count.
// Blocks [0, G1_TILES): hh = x @ W (UNSCALED) -> fp16, 8x4 micro-tile, f32x2.
// Blocks [G1_TILES, +COUNT_BLOCKS): histogram over dst, 4 edges/thread.
// ---------------------------------------------------------------------------
__global__ __launch_bounds__(256) void k_count_gemm(const float* __restrict__ x,
                                                    const float* __restrict__ W,
                                                    const int* __restrict__ ei) {
    __shared__ float Ws[64 * 64];      // k-major
    __shared__ float xs[G1_ROWS][68];

    int tid = threadIdx.x;

    if (blockIdx.x >= G1_TILES) {
        int idx = (blockIdx.x - G1_TILES) * 256 + tid;
        int e4 = idx * 4;
        if (e4 + 3 < N_EDGES) {
            int4 d = *(const int4*)&ei[N_EDGES + e4];
            atomicAdd(&g_cnt[d.x], 1);
            atomicAdd(&g_cnt[d.y], 1);
            atomicAdd(&g_cnt[d.z], 1);
            atomicAdd(&g_cnt[d.w], 1);
        } else {
            for (int j = 0; j < 4; j++)
                if (e4 + j < N_EDGES) atomicAdd(&g_cnt[ei[N_EDGES + e4 + j]], 1);
        }
        return;
    }

    long long rowbase = (long long)blockIdx.x * G1_ROWS;

#pragma unroll
    for (int i = 0; i < 4; i++)
        ((float4*)Ws)[tid + 256 * i] = ((const float4*)W)[tid + 256 * i];

#pragma unroll
    for (int i = 0; i < 8; i++) {
        int f = tid + i * 256;
        int r = f >> 4, kq = f & 15;
        long long grow = rowbase + r;
        float4 v = make_float4(0.f, 0.f, 0.f, 0.f);
        if (grow < N_NODES) v = *(const float4*)&x[grow * 64 + kq * 4];
        *(float4*)&xs[r][kq * 4] = v;
    }
    __syncthreads();

    int tx = tid & 15;
    int ty = tid >> 4;
    int r0 = ty * 8;
    int c0 = tx * 4;

    unsigned long long a01[8], a23[8];
#pragma unroll
    for (int i = 0; i < 8; i++) { a01[i] = 0ull; a23[i] = 0ull; }

#pragma unroll
    for (int k0 = 0; k0 < 64; k0 += 4) {
        float4 xv[8];
#pragma unroll
        for (int i = 0; i < 8; i++) xv[i] = *(float4*)&xs[r0 + i][k0];
#pragma unroll
        for (int kk = 0; kk < 4; kk++) {
            float4 w = *(float4*)&Ws[(k0 + kk) * 64 + c0];
            unsigned long long w01 = pack2(w.x, w.y);
            unsigned long long w23 = pack2(w.z, w.w);
#pragma unroll
            for (int i = 0; i < 8; i++) {
                float xk = (kk == 0) ? xv[i].x : (kk == 1) ? xv[i].y
                         : (kk == 2) ? xv[i].z : xv[i].w;
                unsigned long long xx = pack2(xk, xk);
                a01[i] = ffma2(xx, w01, a01[i]);
                a23[i] = ffma2(xx, w23, a23[i]);
            }
        }
    }

#pragma unroll
    for (int i = 0; i < 8; i++) {
        long long row = rowbase + r0 + i;
        if (row < N_NODES) {
            float b0, b1, b2, b3;
            unpack2(a01[i], b0, b1);
            unpack2(a23[i], b2, b3);
            __half2* dst = &g_hh[row * 32 + (c0 >> 1)];
            dst[0] = __floats2half2_rn(b0, b1);
            dst[1] = __floats2half2_rn(b2, b3);
        }
    }
}

// ---------------------------------------------------------------------------
// K2: single-kernel scan. Block b first sums all counts BEFORE its chunk,
// then block-local scan of its own 1024 counts -> offsets, cursors, dinv.
// ---------------------------------------------------------------------------
__global__ __launch_bounds__(256) void k_scan() {
    __shared__ int wsum[8], woff[8];
    __shared__ int sBase;
    int tid = threadIdx.x;
    int lane = tid & 31, wid = tid >> 5;

    int nPre = blockIdx.x * SCAN_CHUNK;
    int pre = 0;
#pragma unroll 4
    for (int i = tid * 4; i < nPre; i += 256 * 4) {
        int4 v = *(const int4*)&g_cnt[i];
        pre += v.x + v.y + v.z + v.w;
    }
#pragma unroll
    for (int o = 16; o; o >>= 1) pre += __shfl_down_sync(0xFFFFFFFFu, pre, o);
    if (lane == 0) wsum[wid] = pre;
    __syncthreads();
    if (tid == 0) {
        int t = 0;
#pragma unroll
        for (int i = 0; i < 8; i++) t += wsum[i];
        sBase = t;
    }
    __syncthreads();

    int base = blockIdx.x * SCAN_CHUNK + tid * 4;
    int v[4];
    if (base + 3 < N_NODES) {
        int4 t = *(const int4*)&g_cnt[base];
        v[0] = t.x; v[1] = t.y; v[2] = t.z; v[3] = t.w;
    } else {
#pragma unroll
        for (int j = 0; j < 4; j++)
            v[j] = (base + j < N_NODES) ? g_cnt[base + j] : 0;
    }
    int tsum = v[0] + v[1] + v[2] + v[3];

    int inc = tsum;
#pragma unroll
    for (int o = 1; o < 32; o <<= 1) {
        int y = __shfl_up_sync(0xFFFFFFFFu, inc, o);
        if (lane >= o) inc += y;
    }
    if (lane == 31) wsum[wid] = inc;
    __syncthreads();
    if (wid == 0) {
        int s = (lane < 8) ? wsum[lane] : 0;
        int orig = s;
#pragma unroll
        for (int o = 1; o < 8; o <<= 1) {
            int y = __shfl_up_sync(0xFFFFFFFFu, s, o);
            if (lane >= o) s += y;
        }
        if (lane < 8) woff[lane] = s - orig;
    }
    __syncthreads();

    int off = sBase + woff[wid] + (inc - tsum);
#pragma unroll
    for (int j = 0; j < 4; j++) {
        int i = base + j;
        if (i < N_NODES) {
            g_off[i] = off;
            g_cursor[i] = off;
            g_dinv[i] = rsqrtf(1.0f + (float)v[j]);
        }
        off += v[j];
    }
}

// ---------------------------------------------------------------------------
// K3: bucket fill — 1 edge per thread (max independent atomic chains)
// ---------------------------------------------------------------------------
__global__ __launch_bounds__(256) void k_fill(const int* __restrict__ ei) {
    int e = blockIdx.x * 256 + threadIdx.x;
    if (e < N_EDGES) {
        int src = ei[e];
        int dst = ei[N_EDGES + e];
        g_srcs[atomicAdd(&g_cursor[dst], 1)] = src;
    }
}

// ---------------------------------------------------------------------------
// K4: gather + LN + ReLU + x-gate -> g_rs (fp16). LEAN: no GEMM smem, low
// regs for occupancy (gather is latency-bound). 8 warps x 8 nodes, R9-style
// chained 4-unrolled neighbor loop (measured faster than shfl staging).
// ---------------------------------------------------------------------------
__global__ __launch_bounds__(256) void k_gather_ln(
        const float* __restrict__ x,
        const float* __restrict__ b,
        const float* __restrict__ gamma,
        const float* __restrict__ beta) {
    __shared__ float sb[64], sg[64], sbe[64];

    int tid = threadIdx.x;
    long long rowbase = (long long)blockIdx.x * GL_ROWS;

    if (tid < 64) {
        sb[tid] = b[tid];
        sg[tid] = gamma[tid];
        sbe[tid] = beta[tid];
    }
    __syncthreads();

    int w = tid >> 5;
    int l = tid & 31;

#pragma unroll
    for (int rr = 0; rr < 8; rr++) {
        int lr = w * 8 + rr;
        long long row = rowbase + lr;
        if (row < N_NODES) {
            int start = g_off[row];
            int deg = g_cnt[row];
            float dinv = g_dinv[row];

            // self-loop term: h[row] * dinv[row]
            float2 hv = __half22float2(g_hh[row * 32 + l]);
            float ax = hv.x * dinv, ay = hv.y * dinv;

            int e = start, end = start + deg;
            for (; e + 3 < end; e += 4) {
                int s0 = g_srcs[e],     s1 = g_srcs[e + 1];
                int s2 = g_srcs[e + 2], s3 = g_srcs[e + 3];
                float d0 = g_dinv[s0], d1 = g_dinv[s1];
                float d2 = g_dinv[s2], d3 = g_dinv[s3];
                float2 v0 = __half22float2(g_hh[(long long)s0 * 32 + l]);
                float2 v1 = __half22float2(g_hh[(long long)s1 * 32 + l]);
                float2 v2 = __half22float2(g_hh[(long long)s2 * 32 + l]);
                float2 v3 = __half22float2(g_hh[(long long)s3 * 32 + l]);
                ax += v0.x * d0 + v1.x * d1 + v2.x * d2 + v3.x * d3;
                ay += v0.y * d0 + v1.y * d1 + v2.y * d2 + v3.y * d3;
            }
            for (; e < end; e++) {
                int s = g_srcs[e];
                float ds = g_dinv[s];
                float2 v = __half22float2(g_hh[(long long)s * 32 + l]);
                ax += v.x * ds;
                ay += v.y * ds;
            }

            float v0 = ax * dinv + sb[2 * l];
            float v1 = ay * dinv + sb[2 * l + 1];

            float s = v0 + v1;
            float q = v0 * v0 + v1 * v1;
#pragma unroll
            for (int o = 16; o; o >>= 1) {
                s += __shfl_xor_sync(0xFFFFFFFFu, s, o);
                q += __shfl_xor_sync(0xFFFFFFFFu, q, o);
            }
            float mu = s * (1.0f / 64.0f);
            float var = q * (1.0f / 64.0f) - mu * mu;
            float inv = rsqrtf(var + 1e-5f);

            float2 xv = *(const float2*)&x[row * 64 + 2 * l];
            float t0 = fmaxf((v0 - mu) * inv * sg[2 * l]     + sbe[2 * l],     0.f) * xv.x;
            float t1 = fmaxf((v1 - mu) * inv * sg[2 * l + 1] + sbe[2 * l + 1], 0.f) * xv.y;
            g_rs[row * 32 + l] = __floats2half2_rn(t0, t1);
        }
    }
}

// ---------------------------------------------------------------------------
// K5: GEMM2 — out = rs @ fcW + fcb. 128-row tiles, 8x4 micro-tile, f32x2.
// rs staged in smem AS FP16 (17KB; keeps static smem < 48KB, halves
// crossbar bytes on the row operand). Also resets g_cnt for the next run.
// ---------------------------------------------------------------------------
__global__ __launch_bounds__(256) void k_gemm2(const float* __restrict__ fcW,
                                               const float* __restrict__ fcb,
                                               float* __restrict__ out) {
    __shared__ float Ws[64 * 64];          // fcW, k-major
    __shared__ unsigned xs[G2_ROWS][36];   // rs rows as half2 words (+pad)
    __shared__ float sfcb[64];

    int tid = threadIdx.x;
    long long rowbase = (long long)blockIdx.x * G2_ROWS;

#pragma unroll
    for (int i = 0; i < 4; i++)
        ((float4*)Ws)[tid + 256 * i] = ((const float4*)fcW)[tid + 256 * i];
    if (tid < 64) sfcb[tid] = fcb[tid];

    // stage 128x64 rs tile (fp16): 2048 uint2 loads total, 8 per thread
#pragma unroll
    for (int i = 0; i < 8; i++) {
        int f = tid + i * 256;
        int r = f >> 4, kq = f & 15;     // kq indexes pairs of half2 (4 cols)
        long long row = rowbase + r;
        uint2 v = make_uint2(0u, 0u);
        if (row < N_NODES) v = *(const uint2*)&g_rs[row * 32 + kq * 2];
        xs[r][kq * 2] = v.x;
        xs[r][kq * 2 + 1] = v.y;
    }

    // restore g_cnt == 0 for the next run (k_gather_ln is done with it)
    if (tid < G2_ROWS) {
        long long row = rowbase + tid;
        if (row < N_NODES) g_cnt[row] = 0;
    }
    __syncthreads();

    int tx = tid & 15;
    int ty = tid >> 4;
    int r0 = ty * 8;
    int c0 = tx * 4;

    unsigned long long a01[8], a23[8];
#pragma unroll
    for (int i = 0; i < 8; i++) { a01[i] = 0ull; a23[i] = 0ull; }

#pragma unroll
    for (int k0 = 0; k0 < 64; k0 += 4) {
        float4 xv[8];
#pragma unroll
        for (int i = 0; i < 8; i++) {
            uint2 u = *(const uint2*)&xs[r0 + i][k0 >> 1];
            float2 lo = __half22float2(*reinterpret_cast<__half2*>(&u.x));
            float2 hi = __half22float2(*reinterpret_cast<__half2*>(&u.y));
            xv[i] = make_float4(lo.x, lo.y, hi.x, hi.y);
        }
#pragma unroll
        for (int kk = 0; kk < 4; kk++) {
            float4 wv = *(float4*)&Ws[(k0 + kk) * 64 + c0];
            unsigned long long w01 = pack2(wv.x, wv.y);
            unsigned long long w23 = pack2(wv.z, wv.w);
#pragma unroll
            for (int i = 0; i < 8; i++) {
                float xk = (kk == 0) ? xv[i].x : (kk == 1) ? xv[i].y
                         : (kk == 2) ? xv[i].z : xv[i].w;
                unsigned long long xx = pack2(xk, xk);
                a01[i] = ffma2(xx, w01, a01[i]);
                a23[i] = ffma2(xx, w23, a23[i]);
            }
        }
    }

#pragma unroll
    for (int i = 0; i < 8; i++) {
        long long row = rowbase + r0 + i;
        if (row < N_NODES) {
            float b0, b1, b2, b3;
            unpack2(a01[i], b0, b1);
            unpack2(a23[i], b2, b3);
            *(float4*)&out[row * 64 + c0] =
                make_float4(b0 + sfcb[c0], b1 + sfcb[c0 + 1],
                            b2 + sfcb[c0 + 2], b3 + sfcb[c0 + 3]);
        }
    }
}

// ---------------------------------------------------------------------------
extern "C" void kernel_launch(void* const* d_in, const int* in_sizes, int n_in,
                              void* d_out, int out_size) {
    const float* x     = (const float*)d_in[0];
    const int*   ei    = (const int*)d_in[1];   // int32 per harness metadata
    const float* W     = (const float*)d_in[2];
    const float* b     = (const float*)d_in[3];
    const float* gamma = (const float*)d_in[4];
    const float* beta  = (const float*)d_in[5];
    const float* fcW   = (const float*)d_in[6];
    const float* fcb   = (const float*)d_in[7];
    float* out = (float*)d_out;

    (void)in_sizes; (void)n_in; (void)out_size;

    k_count_gemm<<<G1_TILES + COUNT_BLOCKS, 256>>>(x, W, ei);
    k_scan<<<NB_SCAN, 256>>>();
    k_fill<<<FILL_BLOCKS, 256>>>(ei);
    k_gather_ln<<<GL_TILES, 256>>>(x, b, gamma, beta);
    k_gemm2<<<G2_TILES, 256>>>(fcW, fcb, out);
}